// round 2
// baseline (speedup 1.0000x reference)
#include <cuda_runtime.h>
#include <cstdint>

// NonLocalMeansSmoothing: x [8,256,256,8] fp32 -> same shape. K=5, sigma=1, h=1.
// reflect padding.
//
// w ∝ exp(-(||c-n||^2 + 0.5*(di^2+dj^2)))   (Gaussian global norm cancels in renorm)
// ||c-n||^2 = ||c||^2 + ||n||^2 - 2 c·n  with per-pixel norms precomputed in smem.
// Channel math uses sm_103a packed f32x2 (FFMA2) — 2 flops per issue slot.

#define BATCH 8
#define NX 256
#define NY 256
#define TILE 32
#define HALO 2
#define SMW (TILE + 2 * HALO)   // 36

typedef unsigned long long u64;

__device__ __forceinline__ u64 fma2(u64 a, u64 b, u64 c) {
    u64 d; asm("fma.rn.f32x2 %0,%1,%2,%3;" : "=l"(d) : "l"(a), "l"(b), "l"(c)); return d;
}
__device__ __forceinline__ u64 mul2(u64 a, u64 b) {
    u64 d; asm("mul.rn.f32x2 %0,%1,%2;" : "=l"(d) : "l"(a), "l"(b)); return d;
}
__device__ __forceinline__ u64 pack2(float lo, float hi) {
    u64 d; asm("mov.b64 %0,{%1,%2};" : "=l"(d) : "f"(lo), "f"(hi)); return d;
}
__device__ __forceinline__ float hadd2(u64 a) {
    float lo, hi; asm("mov.b64 {%0,%1},%2;" : "=f"(lo), "=f"(hi) : "l"(a));
    return lo + hi;
}
__device__ __forceinline__ float ex2f(float x) {
    float r; asm("ex2.approx.ftz.f32 %0,%1;" : "=f"(r) : "f"(x)); return r;
}

__device__ __forceinline__ int refl(int p, int n) {
    if (p < 0) p = -p;
    if (p >= n) p = 2 * n - 2 - p;
    return p;
}

#define L2E 1.4426950408889634f

__global__ __launch_bounds__(1024, 1)
void nlm_kernel(const float* __restrict__ x, float* __restrict__ out) {
    // Channel planes as 16B vectors; lane-adjacent pixels 16B apart -> conflict-free LDS.128.
    __shared__ ulonglong2 sm0[SMW][SMW];   // channels 0-3 (two f32x2 pairs)
    __shared__ ulonglong2 sm1[SMW][SMW];   // channels 4-7
    __shared__ float      snorm[SMW][SMW]; // per-pixel ||v||^2

    const int b   = blockIdx.z;
    const int ti0 = blockIdx.y * TILE;
    const int tj0 = blockIdx.x * TILE;
    const int tid = threadIdx.y * 32 + threadIdx.x;

    const float* xb = x + (size_t)b * NX * NY * 8;

    // Halo load + norm precompute: 36*36 = 1296 pixels, 1024 threads.
    for (int p = tid; p < SMW * SMW; p += 1024) {
        int r = p / SMW;
        int c = p - r * SMW;
        int gi = refl(ti0 + r - HALO, NX);
        int gj = refl(tj0 + c - HALO, NY);
        const float4* src = reinterpret_cast<const float4*>(
            xb + ((size_t)gi * NY + gj) * 8);
        float4 v0 = src[0];
        float4 v1 = src[1];
        *reinterpret_cast<float4*>(&sm0[r][c]) = v0;
        *reinterpret_cast<float4*>(&sm1[r][c]) = v1;
        float nrm = v0.x * v0.x + v0.y * v0.y + v0.z * v0.z + v0.w * v0.w
                  + v1.x * v1.x + v1.y * v1.y + v1.z * v1.z + v1.w * v1.w;
        snorm[r][c] = nrm;
    }
    __syncthreads();

    const int li = threadIdx.y + HALO;
    const int lj = threadIdx.x + HALO;

    const ulonglong2 C0 = sm0[li][lj];
    const ulonglong2 C1 = sm1[li][lj];
    const float pc = -L2E * snorm[li][lj];   // -log2e * ||c||^2

    u64 acc0a = 0, acc0b = 0, acc1a = 0, acc1b = 0;
    float wsum = 0.f;

#pragma unroll
    for (int di = -HALO; di <= HALO; di++) {
#pragma unroll
        for (int dj = -HALO; dj <= HALO; dj++) {
            const ulonglong2 N0 = sm0[li + di][lj + dj];
            const ulonglong2 N1 = sm1[li + di][lj + dj];
            const float normN = snorm[li + di][lj + dj];

            // c·n over 8 channels: 4 packed ops + horizontal add
            u64 dp = mul2(C0.x, N0.x);
            dp = fma2(C0.y, N0.y, dp);
            dp = fma2(C1.x, N1.x, dp);
            dp = fma2(C1.y, N1.y, dp);
            const float dot = hadd2(dp);

            // exponent = -log2e*(||c||^2 + ||n||^2 - 2 dot + g)
            const float cg = -L2E * (0.5f * (float)(di * di + dj * dj));
            float e = fmaf(-L2E, normN, pc);
            e = fmaf(2.0f * L2E, dot, e);
            const float w = ex2f(e + cg);

            const u64 w2 = pack2(w, w);
            acc0a = fma2(w2, N0.x, acc0a);
            acc0b = fma2(w2, N0.y, acc0b);
            acc1a = fma2(w2, N1.x, acc1a);
            acc1b = fma2(w2, N1.y, acc1b);
            wsum += w;
        }
    }

    const float inv = __fdividef(1.f, wsum);
    const u64 inv2 = pack2(inv, inv);

    ulonglong2 r0, r1;
    r0.x = mul2(acc0a, inv2);
    r0.y = mul2(acc0b, inv2);
    r1.x = mul2(acc1a, inv2);
    r1.y = mul2(acc1b, inv2);

    const int gi = ti0 + threadIdx.y;
    const int gj = tj0 + threadIdx.x;
    ulonglong2* dst = reinterpret_cast<ulonglong2*>(
        out + (((size_t)b * NX + gi) * NY + gj) * 8);
    dst[0] = r0;
    dst[1] = r1;
}

extern "C" void kernel_launch(void* const* d_in, const int* in_sizes, int n_in,
                              void* d_out, int out_size) {
    const float* x = (const float*)d_in[0];
    float* out = (float*)d_out;
    dim3 block(32, 32, 1);
    dim3 grid(NY / TILE, NX / TILE, BATCH);  // (8, 8, 8)
    nlm_kernel<<<grid, block>>>(x, out);
}

// round 3
// speedup vs baseline: 1.2931x; 1.2931x over previous
#include <cuda_runtime.h>
#include <cstdint>

// NonLocalMeansSmoothing: x [8,256,256,8] fp32 -> same. K=5, sigma=1, h=1.
// w ∝ exp(-(||c-n||^2 + 0.5*(di^2+dj^2)))  (gaussian global norm cancels)
// ||c-n||^2 = ||c||^2 + ||n||^2 - 2 c·n, norms pre-scaled by -log2e in smem.
// 2 pixels per thread (vertical pair): 30 neighbor loads serve 50 taps.

#define BATCH 8
#define NX 256
#define NY 256
#define TILE 32
#define HALO 2
#define SMW (TILE + 2 * HALO)   // 36
#define L2E 1.4426950408889634f

typedef unsigned long long u64;

__device__ __forceinline__ u64 fma2(u64 a, u64 b, u64 c) {
    u64 d; asm("fma.rn.f32x2 %0,%1,%2,%3;" : "=l"(d) : "l"(a), "l"(b), "l"(c)); return d;
}
__device__ __forceinline__ u64 mul2(u64 a, u64 b) {
    u64 d; asm("mul.rn.f32x2 %0,%1,%2;" : "=l"(d) : "l"(a), "l"(b)); return d;
}
__device__ __forceinline__ u64 pack2(float lo, float hi) {
    u64 d; asm("mov.b64 %0,{%1,%2};" : "=l"(d) : "f"(lo), "f"(hi)); return d;
}
__device__ __forceinline__ float hadd2(u64 a) {
    float lo, hi; asm("mov.b64 {%0,%1},%2;" : "=f"(lo), "=f"(hi) : "l"(a));
    return lo + hi;
}
__device__ __forceinline__ float ex2f(float x) {
    float r; asm("ex2.approx.ftz.f32 %0,%1;" : "=f"(r) : "f"(x)); return r;
}
__device__ __forceinline__ int refl(int p, int n) {
    if (p < 0) p = -p;
    if (p >= n) p = 2 * n - 2 - p;
    return p;
}

__global__ __launch_bounds__(512, 2)
void nlm_kernel(const float* __restrict__ x, float* __restrict__ out) {
    __shared__ ulonglong2 sm0[SMW][SMW];   // ch 0-3
    __shared__ ulonglong2 sm1[SMW][SMW];   // ch 4-7
    __shared__ float      snl[SMW][SMW];   // -log2e * ||v||^2

    const int b   = blockIdx.z;
    const int ti0 = blockIdx.y * TILE;
    const int tj0 = blockIdx.x * TILE;
    const int tid = threadIdx.y * 32 + threadIdx.x;

    const float* xb = x + (size_t)b * NX * NY * 8;

    // Halo load: 1296 pixels / 512 threads.
    for (int p = tid; p < SMW * SMW; p += 512) {
        int r = p / SMW;
        int c = p - r * SMW;
        int gi = refl(ti0 + r - HALO, NX);
        int gj = refl(tj0 + c - HALO, NY);
        const float4* src = reinterpret_cast<const float4*>(
            xb + ((size_t)gi * NY + gj) * 8);
        float4 v0 = src[0];
        float4 v1 = src[1];
        *reinterpret_cast<float4*>(&sm0[r][c]) = v0;
        *reinterpret_cast<float4*>(&sm1[r][c]) = v1;
        float nrm = v0.x * v0.x + v0.y * v0.y + v0.z * v0.z + v0.w * v0.w
                  + v1.x * v1.x + v1.y * v1.y + v1.z * v1.z + v1.w * v1.w;
        snl[r][c] = -L2E * nrm;
    }
    __syncthreads();

    // Two vertically adjacent pixels per thread.
    const int y0 = 2 * threadIdx.y;            // tile-local row of pixel0
    const int li0 = y0 + HALO;                 // smem row of pixel0
    const int lj  = threadIdx.x + HALO;

    const ulonglong2 C00 = sm0[li0][lj];
    const ulonglong2 C01 = sm1[li0][lj];
    const float      pc0 = snl[li0][lj];
    const ulonglong2 C10 = sm0[li0 + 1][lj];
    const ulonglong2 C11 = sm1[li0 + 1][lj];
    const float      pc1 = snl[li0 + 1][lj];

    u64 p0a = 0, p0b = 0, p0c = 0, p0d = 0;
    u64 p1a = 0, p1b = 0, p1c = 0, p1d = 0;
    float ws0 = 0.f, ws1 = 0.f;

    // Window rows r = 0..5 map to smem rows 2*ty + r.
    // pixel0 uses r in [0,4] (di0 = r-2); pixel1 uses r in [1,5] (di1 = r-3).
#pragma unroll
    for (int r = 0; r < 6; r++) {
#pragma unroll
        for (int dj = -HALO; dj <= HALO; dj++) {
            const int sr = y0 + r;
            const ulonglong2 N0 = sm0[sr][lj + dj];
            const ulonglong2 N1 = sm1[sr][lj + dj];
            const float ns = snl[sr][lj + dj];

            if (r <= 4) {
                const int di = r - 2;
                const float cg = -L2E * (0.5f * (float)(di * di + dj * dj));
                u64 dp = mul2(C00.x, N0.x);
                dp = fma2(C00.y, N0.y, dp);
                dp = fma2(C01.x, N1.x, dp);
                dp = fma2(C01.y, N1.y, dp);
                float e = fmaf(2.0f * L2E, hadd2(dp), pc0 + ns);
                const float w = ex2f(e + cg);
                const u64 w2 = pack2(w, w);
                p0a = fma2(w2, N0.x, p0a);
                p0b = fma2(w2, N0.y, p0b);
                p0c = fma2(w2, N1.x, p0c);
                p0d = fma2(w2, N1.y, p0d);
                ws0 += w;
            }
            if (r >= 1) {
                const int di = r - 3;
                const float cg = -L2E * (0.5f * (float)(di * di + dj * dj));
                u64 dp = mul2(C10.x, N0.x);
                dp = fma2(C10.y, N0.y, dp);
                dp = fma2(C11.x, N1.x, dp);
                dp = fma2(C11.y, N1.y, dp);
                float e = fmaf(2.0f * L2E, hadd2(dp), pc1 + ns);
                const float w = ex2f(e + cg);
                const u64 w2 = pack2(w, w);
                p1a = fma2(w2, N0.x, p1a);
                p1b = fma2(w2, N0.y, p1b);
                p1c = fma2(w2, N1.x, p1c);
                p1d = fma2(w2, N1.y, p1d);
                ws1 += w;
            }
        }
    }

    const int gi0 = ti0 + y0;
    const int gj  = tj0 + threadIdx.x;

    {
        const float inv = __fdividef(1.f, ws0);
        const u64 inv2 = pack2(inv, inv);
        ulonglong2 r0, r1;
        r0.x = mul2(p0a, inv2); r0.y = mul2(p0b, inv2);
        r1.x = mul2(p0c, inv2); r1.y = mul2(p0d, inv2);
        ulonglong2* dst = reinterpret_cast<ulonglong2*>(
            out + (((size_t)b * NX + gi0) * NY + gj) * 8);
        dst[0] = r0; dst[1] = r1;
    }
    {
        const float inv = __fdividef(1.f, ws1);
        const u64 inv2 = pack2(inv, inv);
        ulonglong2 r0, r1;
        r0.x = mul2(p1a, inv2); r0.y = mul2(p1b, inv2);
        r1.x = mul2(p1c, inv2); r1.y = mul2(p1d, inv2);
        ulonglong2* dst = reinterpret_cast<ulonglong2*>(
            out + (((size_t)b * NX + gi0 + 1) * NY + gj) * 8);
        dst[0] = r0; dst[1] = r1;
    }
}

extern "C" void kernel_launch(void* const* d_in, const int* in_sizes, int n_in,
                              void* d_out, int out_size) {
    const float* x = (const float*)d_in[0];
    float* out = (float*)d_out;
    dim3 block(32, 16, 1);
    dim3 grid(NY / TILE, NX / TILE, BATCH);  // (8, 8, 8)
    nlm_kernel<<<grid, block>>>(x, out);
}